// round 15
// baseline (speedup 1.0000x reference)
#include <cuda_runtime.h>
#include <cuda_bf16.h>
#include <math.h>
#include <stdint.h>

#define BB 4
#define NN 512
#define DIM 512
#define HEADS 8
#define DH 64
#define DEPTH 4
#define ROWS (BB*NN)
#define ATT_SCALE 0.125f
#define LN_EPS 1e-5f
#define PLN (ROWS*DIM)          // 1048576
#define WPL (DEPTH*DIM*DIM)     // 1048576

// ---------------- scratch ----------------------------------------------------
__device__ float g_x_r [PLN];
__device__ float g_x_i [PLN];
__device__ float g_xn_r[PLN];
__device__ float g_xn_i[PLN];
// bf16 planes: 0=re_hi 1=re_lo 2=im_hi 3=im_lo
__device__ alignas(16) __nv_bfloat16 g_xnb [4*PLN];
__device__ alignas(16) __nv_bfloat16 g_wb  [4*PLN];
__device__ alignas(16) __nv_bfloat16 g_atb [4*PLN];
__device__ alignas(16) __nv_bfloat16 g_qkvb[4*WPL];
__device__ alignas(16) __nv_bfloat16 g_outb[4*WPL];
__device__ alignas(16) __nv_bfloat16 g_ffb [4*WPL];

// ---------------- helpers -----------------------------------------------------
__device__ __forceinline__ float warp_sum(float v){
    #pragma unroll
    for (int o=16;o;o>>=1) v += __shfl_xor_sync(0xffffffffu, v, o);
    return v;
}
__device__ __forceinline__ void cpa16(unsigned dst, const void* src){
    asm volatile("cp.async.cg.shared.global [%0], [%1], 16;" :: "r"(dst), "l"(src));
}
#define CP_COMMIT() asm volatile("cp.async.commit_group;")
#define CP_WAIT1()  asm volatile("cp.async.wait_group 1;")
#define CP_WAIT0()  asm volatile("cp.async.wait_group 0;")

__device__ __forceinline__ void ldsm4(unsigned &r0,unsigned &r1,unsigned &r2,unsigned &r3,unsigned a){
    asm volatile("ldmatrix.sync.aligned.m8n8.x4.shared.b16 {%0,%1,%2,%3}, [%4];"
        : "=r"(r0),"=r"(r1),"=r"(r2),"=r"(r3) : "r"(a));
}
__device__ __forceinline__ void ldsm4t(unsigned &r0,unsigned &r1,unsigned &r2,unsigned &r3,unsigned a){
    asm volatile("ldmatrix.sync.aligned.m8n8.x4.trans.shared.b16 {%0,%1,%2,%3}, [%4];"
        : "=r"(r0),"=r"(r1),"=r"(r2),"=r"(r3) : "r"(a));
}
__device__ __forceinline__ void mmabf(float* d, const unsigned* a, const unsigned* b){
    asm volatile("mma.sync.aligned.m16n8k16.row.col.f32.bf16.bf16.f32 "
        "{%0,%1,%2,%3}, {%4,%5,%6,%7}, {%8,%9}, {%0,%1,%2,%3};"
        : "+f"(d[0]),"+f"(d[1]),"+f"(d[2]),"+f"(d[3])
        : "r"(a[0]),"r"(a[1]),"r"(a[2]),"r"(a[3]), "r"(b[0]),"r"(b[1]));
}

__device__ __forceinline__ float frsqrt(float d){
    float x = __int_as_float(0x5f3759df - (__float_as_int(d) >> 1));
    x = x * fmaf(-0.5f*d, x*x, 1.5f);
    x = x * fmaf(-0.5f*d, x*x, 1.5f);
    return x;
}
__device__ __forceinline__ float fexp(float x){
    x = fmaxf(x, -87.0f);
    const float y = x * 1.4426950408889634f;
    const int   n = __float2int_rn(y);
    const float f = y - (float)n;
    float p = 1.3333558146e-3f;
    p = fmaf(p, f, 9.6181291076e-3f);
    p = fmaf(p, f, 5.5504108665e-2f);
    p = fmaf(p, f, 2.4022650696e-1f);
    p = fmaf(p, f, 6.9314718056e-1f);
    p = fmaf(p, f, 1.0f);
    return p * __int_as_float((n + 127) << 23);
}

__device__ __forceinline__ void split2(float x, float y, unsigned &hi, unsigned &lo){
    __nv_bfloat16 hx=__float2bfloat16_rn(x), hy=__float2bfloat16_rn(y);
    __nv_bfloat162 H = __halves2bfloat162(hx, hy);
    hi = *reinterpret_cast<unsigned*>(&H);
    __nv_bfloat16 lx=__float2bfloat16_rn(x-__bfloat162float(hx));
    __nv_bfloat16 ly=__float2bfloat16_rn(y-__bfloat162float(hy));
    __nv_bfloat162 L = __halves2bfloat162(lx, ly);
    lo = *reinterpret_cast<unsigned*>(&L);
}
__device__ __forceinline__ void store_split4(__nv_bfloat16* p, size_t pl, size_t o, float4 v){
    unsigned hi, lo;
    split2(v.x, v.y, hi, lo);
    *(unsigned*)(p+o) = hi; *(unsigned*)(p+pl+o) = lo;
    split2(v.z, v.w, hi, lo);
    *(unsigned*)(p+o+2) = hi; *(unsigned*)(p+pl+o+2) = lo;
}

// ---------------- small kernels -----------------------------------------------
__global__ void copy_in_kernel(const float* __restrict__ a, const float* __restrict__ b,
                               float* __restrict__ xr, float* __restrict__ xi, int n){
    int i = blockIdx.x*blockDim.x + threadIdx.x;
    if (i < n){ xr[i] = a[i]; xi[i] = b[i]; }
}
__global__ void copy_out_kernel(const float* __restrict__ xr, const float* __restrict__ xi,
                                float* __restrict__ out, int n){
    int i = blockIdx.x*blockDim.x + threadIdx.x;
    if (i < n){ out[i] = xr[i]; out[n+i] = xi[i]; }
}
__global__ void conv_split_kernel(const float* __restrict__ r, const float* __restrict__ im,
                                  __nv_bfloat16* __restrict__ dst, int n){
    int x = blockIdx.x*blockDim.x + threadIdx.x;
    if (x >= n) return;
    float v = r[x];
    __nv_bfloat16 h = __float2bfloat16_rn(v);
    dst[x] = h; dst[n + x] = __float2bfloat16_rn(v - __bfloat162float(h));
    v = im[x];
    h = __float2bfloat16_rn(v);
    dst[2*(size_t)n + x] = h; dst[3*(size_t)n + x] = __float2bfloat16_rn(v - __bfloat162float(h));
}

template<bool WF32>
__global__ __launch_bounds__(128)
void cln_kernel(const float* __restrict__ xr, const float* __restrict__ xi,
                const float* __restrict__ gr, const float* __restrict__ br,
                const float* __restrict__ gi, const float* __restrict__ bi,
                float* __restrict__ outr, float* __restrict__ outi,
                __nv_bfloat16* __restrict__ outb)
{
    const int row = blockIdx.x;
    const int t   = threadIdx.x;
    const float4 vr = reinterpret_cast<const float4*>(xr + (size_t)row*DIM)[t];
    const float4 vi = reinterpret_cast<const float4*>(xi + (size_t)row*DIM)[t];

    float sr  = vr.x+vr.y+vr.z+vr.w;
    float s2r = vr.x*vr.x+vr.y*vr.y+vr.z*vr.z+vr.w*vr.w;
    float si  = vi.x+vi.y+vi.z+vi.w;
    float s2i = vi.x*vi.x+vi.y*vi.y+vi.z*vi.z+vi.w*vi.w;

    sr = warp_sum(sr); s2r = warp_sum(s2r); si = warp_sum(si); s2i = warp_sum(s2i);

    __shared__ float red[4][4];
    const int wid = t >> 5, lane = t & 31;
    if (lane == 0){ red[wid][0]=sr; red[wid][1]=s2r; red[wid][2]=si; red[wid][3]=s2i; }
    __syncthreads();
    float tr=0,t2r=0,ti=0,t2i=0;
    #pragma unroll
    for (int w=0; w<4; w++){ tr+=red[w][0]; t2r+=red[w][1]; ti+=red[w][2]; t2i+=red[w][3]; }

    const float inv = 1.0f/DIM;
    const float mr = tr*inv,  vvr = t2r*inv - mr*mr;
    const float mi = ti*inv,  vvi = t2i*inv - mi*mi;
    const float rr = rsqrtf(vvr + LN_EPS);
    const float ri = rsqrtf(vvi + LN_EPS);

    const float4 g4r = reinterpret_cast<const float4*>(gr)[t];
    const float4 b4r = reinterpret_cast<const float4*>(br)[t];
    const float4 g4i = reinterpret_cast<const float4*>(gi)[t];
    const float4 b4i = reinterpret_cast<const float4*>(bi)[t];

    float4 orr, oii;
    orr.x = (vr.x-mr)*rr*g4r.x + b4r.x;  oii.x = (vi.x-mi)*ri*g4i.x + b4i.x;
    orr.y = (vr.y-mr)*rr*g4r.y + b4r.y;  oii.y = (vi.y-mi)*ri*g4i.y + b4i.y;
    orr.z = (vr.z-mr)*rr*g4r.z + b4r.z;  oii.z = (vi.z-mi)*ri*g4i.z + b4i.z;
    orr.w = (vr.w-mr)*rr*g4r.w + b4r.w;  oii.w = (vi.w-mi)*ri*g4i.w + b4i.w;
    if (WF32){
        reinterpret_cast<float4*>(outr + (size_t)row*DIM)[t] = orr;
        reinterpret_cast<float4*>(outi + (size_t)row*DIM)[t] = oii;
    }

    const size_t o = (size_t)row*DIM + 4*t;
    store_split4(outb,                 PLN, o, orr);
    store_split4(outb + (size_t)2*PLN, PLN, o, oii);
}

// ================= fused attention (dots + csoftmax + attn@V) ==================
#define RSQ 144
#define QPLANE (128*RSQ)
#define KVPLANE (64*RSQ)
#define KVSTAGE (4*KVPLANE)
#define FUSED_SMEM (4*QPLANE + 2*KVSTAGE)   // 147456

__global__ __launch_bounds__(256, 1)
void fused_attn_kernel(const __nv_bfloat16* __restrict__ wb,
                       __nv_bfloat16* __restrict__ atb)
{
    extern __shared__ char dsmc[];
    const unsigned smQ  = ((unsigned)__cvta_generic_to_shared(dsmc) + 127u) & ~127u;
    const unsigned smKV = smQ + 4*QPLANE;

    const int tid = threadIdx.x;
    const int lane = tid & 31, wid = tid >> 5;
    const int wrow = wid * 16;
    const int m0 = blockIdx.x * 128;
    const int zb = blockIdx.y >> 3, zh = blockIdx.y & 7;
    const int qrow0 = zb*NN + m0;
    const int brow0 = zb*NN;
    const int colh  = zh*DH;

    #pragma unroll
    for (int t = 0; t < 16; t++){
        const int idx = tid + t*256;
        const int p = idx >> 10, rem = idx & 1023;
        const int r = rem >> 3, cc = rem & 7;
        cpa16(smQ + p*QPLANE + r*RSQ + cc*16,
              wb + (size_t)p*PLN + (size_t)(qrow0 + r)*DIM + colh + cc*8);
    }
    #pragma unroll
    for (int t = 0; t < 8; t++){
        const int idx = tid + t*256;
        const int p = idx >> 9, rem = idx & 511;
        const int r = rem >> 3, cc = rem & 7;
        cpa16(smKV + p*KVPLANE + r*RSQ + cc*16,
              wb + (size_t)p*PLN + (size_t)(brow0 + r)*DIM + colh + cc*8);
    }
    CP_COMMIT();

    float ore[8][4] = {}, oim[8][4] = {};
    float LA = 0.f, LB = 0.f;

    const int bg = lane >> 3;
    const int krow = (lane & 7) + ((lane >> 3) & 1)*8;
    const int nc8  = lane >> 4;

    for (int j = 0; j < 8; j++){
        CP_WAIT0();
        __syncthreads();
        const unsigned kvb = smKV + (unsigned)(j & 1)*KVSTAGE;
        if (j + 1 < 8){
            const unsigned kvn = smKV + (unsigned)((j+1) & 1)*KVSTAGE;
            #pragma unroll
            for (int t = 0; t < 8; t++){
                const int idx = tid + t*256;
                const int p = idx >> 9, rem = idx & 511;
                const int r = rem >> 3, cc = rem & 7;
                cpa16(kvn + p*KVPLANE + r*RSQ + cc*16,
                      wb + (size_t)p*PLN + (size_t)(brow0 + (j+1)*64 + r)*DIM + colh + cc*8);
            }
        }
        CP_COMMIT();

        float sre[8][4] = {}, sim[8][4] = {};
        #pragma unroll
        for (int kk = 0; kk < 4; kk++){
            unsigned qrh[4],qrl[4],qih[4],qil[4];
            const unsigned qa = smQ + (unsigned)(wrow + (lane & 15))*RSQ + kk*32 + (lane >> 4)*16;
            ldsm4(qrh[0],qrh[1],qrh[2],qrh[3], qa);
            ldsm4(qrl[0],qrl[1],qrl[2],qrl[3], qa + QPLANE);
            ldsm4(qih[0],qih[1],qih[2],qih[3], qa + 2*QPLANE);
            ldsm4(qil[0],qil[1],qil[2],qil[3], qa + 3*QPLANE);
            #pragma unroll
            for (int np = 0; np < 4; np++){
                const unsigned kb = kvb + (unsigned)(np*16 + ((bg & 2) << 2) + (lane & 7))*RSQ
                                        + kk*32 + (bg & 1)*16;
                unsigned krh[4],krl[4],kih[4],kil[4];
                ldsm4(krh[0],krh[1],krh[2],krh[3], kb);
                ldsm4(krl[0],krl[1],krl[2],krl[3], kb + KVPLANE);
                ldsm4(kih[0],kih[1],kih[2],kih[3], kb + 2*KVPLANE);
                ldsm4(kil[0],kil[1],kil[2],kil[3], kb + 3*KVPLANE);
                #pragma unroll
                for (int f = 0; f < 2; f++){
                    const int nf = 2*np + f;
                    unsigned bh[2] = {krh[2*f], krh[2*f+1]}, bl[2] = {krl[2*f], krl[2*f+1]};
                    unsigned ch[2] = {kih[2*f], kih[2*f+1]}, cl[2] = {kil[2*f], kil[2*f+1]};
                    mmabf(sre[nf], qrh, bh); mmabf(sre[nf], qrh, bl); mmabf(sre[nf], qrl, bh);
                    mmabf(sim[nf], qih, bh); mmabf(sim[nf], qih, bl); mmabf(sim[nf], qil, bh);
                    mmabf(sre[nf], qih, ch); mmabf(sre[nf], qih, cl); mmabf(sre[nf], qil, ch);
                    ch[0]^=0x80008000u; ch[1]^=0x80008000u; cl[0]^=0x80008000u; cl[1]^=0x80008000u;
                    mmabf(sim[nf], qrh, ch); mmabf(sim[nf], qrh, cl); mmabf(sim[nf], qrl, ch);
                }
            }
        }

        // single-pass softmax weights (no max subtraction; |m| bounded well below 88)
        #pragma unroll
        for (int nf = 0; nf < 8; nf++){
            #pragma unroll
            for (int q = 0; q < 4; q++){
                const float dd = sre[nf][q]*sre[nf][q] + sim[nf][q]*sim[nf][q];
                const float rs = frsqrt(dd);
                const float m  = (dd > 0.f) ? ATT_SCALE*dd*rs : 0.f;
                const float e  = fexp(m);
                const bool ok  = (dd > 0.f);
                const float pr = ok ? e*sre[nf][q]*rs : e;
                const float pi = ok ? e*sim[nf][q]*rs : 0.f;
                sre[nf][q] = pr; sim[nf][q] = pi;
                if (q < 2) LA += e; else LB += e;
            }
        }

        #pragma unroll
        for (int kt = 0; kt < 4; kt++){
            unsigned prh[4],prl[4],pih[4],pil[4];
            split2(sre[2*kt][0],   sre[2*kt][1],   prh[0], prl[0]);
            split2(sre[2*kt][2],   sre[2*kt][3],   prh[1], prl[1]);
            split2(sre[2*kt+1][0], sre[2*kt+1][1], prh[2], prl[2]);
            split2(sre[2*kt+1][2], sre[2*kt+1][3], prh[3], prl[3]);
            split2(sim[2*kt][0],   sim[2*kt][1],   pih[0], pil[0]);
            split2(sim[2*kt][2],   sim[2*kt][3],   pih[1], pil[1]);
            split2(sim[2*kt+1][0], sim[2*kt+1][1], pih[2], pil[2]);
            split2(sim[2*kt+1][2], sim[2*kt+1][3], pih[3], pil[3]);
            #pragma unroll
            for (int np2 = 0; np2 < 4; np2++){
                const unsigned vb = kvb + (unsigned)(kt*16 + krow)*RSQ
                                        + (unsigned)(np2*16 + nc8*8)*2;
                unsigned vrh[4],vrl[4],vih[4],vil[4];
                ldsm4t(vrh[0],vrh[1],vrh[2],vrh[3], vb);
                ldsm4t(vrl[0],vrl[1],vrl[2],vrl[3], vb + KVPLANE);
                ldsm4t(vih[0],vih[1],vih[2],vih[3], vb + 2*KVPLANE);
                ldsm4t(vil[0],vil[1],vil[2],vil[3], vb + 3*KVPLANE);
                #pragma unroll
                for (int f = 0; f < 2; f++){
                    const int nf = 2*np2 + f;
                    unsigned bh[2] = {vrh[2*f], vrh[2*f+1]}, bl[2] = {vrl[2*f], vrl[2*f+1]};
                    unsigned ch[2] = {vih[2*f], vih[2*f+1]}, cl[2] = {vil[2*f], vil[2*f+1]};
                    mmabf(ore[nf], prh, bh); mmabf(ore[nf], prh, bl); mmabf(ore[nf], prl, bh);
                    mmabf(oim[nf], pih, bh); mmabf(oim[nf], pih, bl); mmabf(oim[nf], pil, bh);
                    mmabf(oim[nf], prh, ch); mmabf(oim[nf], prh, cl); mmabf(oim[nf], prl, ch);
                    ch[0]^=0x80008000u; ch[1]^=0x80008000u; cl[0]^=0x80008000u; cl[1]^=0x80008000u;
                    mmabf(ore[nf], pih, ch); mmabf(ore[nf], pih, cl); mmabf(ore[nf], pil, ch);
                }
            }
        }
    }

    // reduce row sums across the quad once, then normalize and write
    LA += __shfl_xor_sync(0xffffffffu, LA, 1);
    LA += __shfl_xor_sync(0xffffffffu, LA, 2);
    LB += __shfl_xor_sync(0xffffffffu, LB, 1);
    LB += __shfl_xor_sync(0xffffffffu, LB, 2);
    const float invA = 1.0f / LA, invB = 1.0f / LB;
    const int gA = qrow0 + wrow + (lane >> 2);
    const int gB = gA + 8;
    #pragma unroll
    for (int nf = 0; nf < 8; nf++){
        const int c = colh + nf*8 + (lane & 3)*2;
        const size_t aA = (size_t)gA*DIM + c;
        const size_t aB = (size_t)gB*DIM + c;
        unsigned hi, lo;
        split2(ore[nf][0]*invA, ore[nf][1]*invA, hi, lo);
        *(unsigned*)(atb + aA) = hi; *(unsigned*)(atb + PLN + aA) = lo;
        split2(oim[nf][0]*invA, oim[nf][1]*invA, hi, lo);
        *(unsigned*)(atb + 2*(size_t)PLN + aA) = hi; *(unsigned*)(atb + 3*(size_t)PLN + aA) = lo;
        split2(ore[nf][2]*invB, ore[nf][3]*invB, hi, lo);
        *(unsigned*)(atb + aB) = hi; *(unsigned*)(atb + PLN + aB) = lo;
        split2(oim[nf][2]*invB, oim[nf][3]*invB, hi, lo);
        *(unsigned*)(atb + 2*(size_t)PLN + aB) = hi; *(unsigned*)(atb + 3*(size_t)PLN + aB) = lo;
    }
}

// ================= mma.sync bf16 complex GEMM (dense, 128x64, BK=16, occ 2) ====
#define RS 48                           // 32B data + 16B pad
#define APLANE (128*RS)                 // 6144
#define BPLANE (64*RS)                  // 3072
#define STAGE_B (4*APLANE + 4*BPLANE)   // 36864
#define NSTG 3
#define DSMEM_BYTES (NSTG*STAGE_B + 128)  // 110720 -> 2 CTAs/SM

__device__ __forceinline__ void load_stage(unsigned sb,
    const __nv_bfloat16* A, size_t ap, int lda,
    const __nv_bfloat16* B, size_t bp, int ldb, int k0, int tid)
{
    const int row = tid >> 1, half = tid & 1;
    #pragma unroll
    for (int p=0;p<4;p++)
        cpa16(sb + p*APLANE + row*RS + half*16, A + (size_t)p*ap + (size_t)row*lda + k0 + half*8);
    if (tid < 128){
        #pragma unroll
        for (int p=0;p<4;p++)
            cpa16(sb + 4*APLANE + p*BPLANE + row*RS + half*16, B + (size_t)p*bp + (size_t)row*ldb + k0 + half*8);
    }
    CP_COMMIT();
}

__device__ __forceinline__ void compute_stage(unsigned sb, int wm, int wn, int lane,
    float cre[2][4][4], float cim[2][4][4])
{
    const unsigned aoff = (unsigned)((lane & 15)*RS + (lane >> 4)*16);
    const int bg = lane >> 3;
    const unsigned boff  = (unsigned)((((bg & 2) << 2) + (lane & 7))*RS + (bg & 1)*16);

    unsigned Arh[2][4], Arl[2][4], Aih[2][4], Ail[2][4];
    #pragma unroll
    for (int mf=0; mf<2; mf++){
        const unsigned ab = sb + (unsigned)(wm + mf*16)*RS + aoff;
        ldsm4(Arh[mf][0],Arh[mf][1],Arh[mf][2],Arh[mf][3], ab);
        ldsm4(Arl[mf][0],Arl[mf][1],Arl[mf][2],Arl[mf][3], ab + APLANE);
        ldsm4(Aih[mf][0],Aih[mf][1],Aih[mf][2],Aih[mf][3], ab + 2*APLANE);
        ldsm4(Ail[mf][0],Ail[mf][1],Ail[mf][2],Ail[mf][3], ab + 3*APLANE);
    }
    unsigned Bh[4][2], Bl[4][2];
    #pragma unroll
    for (int np=0; np<2; np++){
        const unsigned bb = sb + 4*APLANE + (unsigned)(wn + np*16)*RS + boff;
        unsigned r0,r1,r2,r3;
        ldsm4(r0,r1,r2,r3, bb);
        Bh[2*np][0]=r0; Bh[2*np][1]=r1; Bh[2*np+1][0]=r2; Bh[2*np+1][1]=r3;
        ldsm4(r0,r1,r2,r3, bb + BPLANE);
        Bl[2*np][0]=r0; Bl[2*np][1]=r1; Bl[2*np+1][0]=r2; Bl[2*np+1][1]=r3;
    }
    #pragma unroll
    for (int mf=0; mf<2; mf++)
    #pragma unroll
    for (int nf=0; nf<4; nf++){
        mmabf(cre[mf][nf], Arh[mf], Bh[nf]);
        mmabf(cre[mf][nf], Arh[mf], Bl[nf]);
        mmabf(cre[mf][nf], Arl[mf], Bh[nf]);
        mmabf(cim[mf][nf], Aih[mf], Bh[nf]);
        mmabf(cim[mf][nf], Aih[mf], Bl[nf]);
        mmabf(cim[mf][nf], Ail[mf], Bh[nf]);
    }
    #pragma unroll
    for (int np=0; np<2; np++){
        const unsigned bb = sb + 4*APLANE + 2*BPLANE + (unsigned)(wn + np*16)*RS + boff;
        unsigned r0,r1,r2,r3;
        ldsm4(r0,r1,r2,r3, bb);
        Bh[2*np][0]=r0; Bh[2*np][1]=r1; Bh[2*np+1][0]=r2; Bh[2*np+1][1]=r3;
        ldsm4(r0,r1,r2,r3, bb + BPLANE);
        Bl[2*np][0]=r0; Bl[2*np][1]=r1; Bl[2*np+1][0]=r2; Bl[2*np+1][1]=r3;
    }
    #pragma unroll
    for (int mf=0; mf<2; mf++)
    #pragma unroll
    for (int nf=0; nf<4; nf++){
        mmabf(cim[mf][nf], Arh[mf], Bh[nf]);
        mmabf(cim[mf][nf], Arh[mf], Bl[nf]);
        mmabf(cim[mf][nf], Arl[mf], Bh[nf]);
    }
    #pragma unroll
    for (int nf=0; nf<4; nf++){
        Bh[nf][0]^=0x80008000u; Bh[nf][1]^=0x80008000u;
        Bl[nf][0]^=0x80008000u; Bl[nf][1]^=0x80008000u;
    }
    #pragma unroll
    for (int mf=0; mf<2; mf++)
    #pragma unroll
    for (int nf=0; nf<4; nf++){
        mmabf(cre[mf][nf], Aih[mf], Bh[nf]);
        mmabf(cre[mf][nf], Aih[mf], Bl[nf]);
        mmabf(cre[mf][nf], Ail[mf], Bh[nf]);
    }
}

// EPI: 0=planes out, 3=OUT (x+=acc+bias), 4=FF (crelu)
template<int EPI>
__global__ __launch_bounds__(256, 2)
void mma_gemm(const __nv_bfloat16* __restrict__ Ab, size_t ap, int lda,
              const __nv_bfloat16* __restrict__ Bb, size_t bp, int ldb,
              int K,
              float* Cr, float* Ci, int ldc,
              __nv_bfloat16* Ob, size_t op,
              const float* __restrict__ biasR, const float* __restrict__ biasI,
              const float* __restrict__ Xr, const float* __restrict__ Xi,
              const float* __restrict__ ssp, const float* __restrict__ lmp, int layer)
{
    extern __shared__ char dsmc[];
    const unsigned base = ((unsigned)__cvta_generic_to_shared(dsmc) + 127u) & ~127u;

    const int tid = threadIdx.x;
    const int lane = tid & 31, wid = tid >> 5;
    const int wm = (wid & 3)*32, wn = (wid >> 2)*32;
    const int m0 = blockIdx.y * 128, n0 = blockIdx.x * 64;

    const __nv_bfloat16* At = Ab + (size_t)m0*lda;
    const __nv_bfloat16* Bt = Bb + (size_t)n0*ldb;

    float cre[2][4][4] = {}, cim[2][4][4] = {};

    const int NIT = K >> 4;
    load_stage(base, At, ap, lda, Bt, bp, ldb, 0, tid);
    if (NIT > 1) load_stage(base + STAGE_B, At, ap, lda, Bt, bp, ldb, 16, tid);
    else CP_COMMIT();

    int sidx = 0;
    for (int it = 0; it < NIT; it++){
        if (it + 1 < NIT) CP_WAIT1(); else CP_WAIT0();
        __syncthreads();
        if (it + 2 < NIT){
            int sn = sidx + 2; if (sn >= NSTG) sn -= NSTG;
            load_stage(base + (unsigned)sn*STAGE_B, At, ap, lda, Bt, bp, ldb, (it+2) << 4, tid);
        } else {
            CP_COMMIT();
        }
        compute_stage(base + (unsigned)sidx*STAGE_B, wm, wn, lane, cre, cim);
        sidx++; if (sidx == NSTG) sidx = 0;
    }

    float ss = 0.f, lm = 0.f;
    if (EPI == 4){ ss = log1pf(expf(ssp[layer])); lm = log1pf(expf(lmp[layer])); }

    #pragma unroll
    for (int mf=0; mf<2; mf++)
    #pragma unroll
    for (int nf=0; nf<4; nf++){
        const int row0 = m0 + wm + mf*16 + (lane >> 2);
        const int col  = n0 + wn + nf*8 + (lane & 3)*2;
        #pragma unroll
        for (int h=0; h<2; h++){
            const int r = row0 + h*8;
            float vr0 = cre[mf][nf][2*h];
            float vr1 = cre[mf][nf][2*h+1];
            float vi0 = cim[mf][nf][2*h];
            float vi1 = cim[mf][nf][2*h+1];
            const size_t a = (size_t)r*ldc + col;
            if (EPI == 3){
                Cr[a]   = vr0 + biasR[col]   + Cr[a];
                Cr[a+1] = vr1 + biasR[col+1] + Cr[a+1];
                Ci[a]   = vi0 + biasI[col]   + Ci[a];
                Ci[a+1] = vi1 + biasI[col+1] + Ci[a+1];
            } else if (EPI == 4){
                Cr[a]   = fmaxf(fmaf(ss, vr0, Xr[a])   - ss*lm, 0.f);
                Cr[a+1] = fmaxf(fmaf(ss, vr1, Xr[a+1]) - ss*lm, 0.f);
                Ci[a]   = fmaxf(fmaf(ss, vi0, Xi[a]),   0.f);
                Ci[a+1] = fmaxf(fmaf(ss, vi1, Xi[a+1]), 0.f);
            } else {
                unsigned hi, lo;
                split2(vr0, vr1, hi, lo);
                *(unsigned*)(Ob + a) = hi; *(unsigned*)(Ob + op + a) = lo;
                split2(vi0, vi1, hi, lo);
                *(unsigned*)(Ob + 2*op + a) = hi; *(unsigned*)(Ob + 3*op + a) = lo;
            }
        }
    }
}

// ---------------- launch --------------------------------------------------------
extern "C" void kernel_launch(void* const* d_in, const int* in_sizes, int n_in,
                              void* d_out, int out_size)
{
    const float* x_real   = (const float*)d_in[0];
    const float* x_imag   = (const float*)d_in[1];
    const float* ln1_g_r  = (const float*)d_in[2];
    const float* ln1_b_r  = (const float*)d_in[3];
    const float* ln1_g_i  = (const float*)d_in[4];
    const float* ln1_b_i  = (const float*)d_in[5];
    const float* ln2_g_r  = (const float*)d_in[6];
    const float* ln2_b_r  = (const float*)d_in[7];
    const float* ln2_g_i  = (const float*)d_in[8];
    const float* ln2_b_i  = (const float*)d_in[9];
    const float* qkv_w_r  = (const float*)d_in[10];
    const float* qkv_w_i  = (const float*)d_in[11];
    const float* out_w_r  = (const float*)d_in[12];
    const float* out_w_i  = (const float*)d_in[13];
    const float* out_b_r  = (const float*)d_in[14];
    const float* out_b_i  = (const float*)d_in[15];
    const float* ff_w_r   = (const float*)d_in[16];
    const float* ff_w_i   = (const float*)d_in[17];
    const float* step_sz  = (const float*)d_in[18];
    const float* lambd    = (const float*)d_in[19];

    float *xr,*xi,*xnr,*xni;
    __nv_bfloat16 *xnb,*wb,*atb,*qkvb,*outb,*ffb;
    cudaGetSymbolAddress((void**)&xr,   g_x_r);
    cudaGetSymbolAddress((void**)&xi,   g_x_i);
    cudaGetSymbolAddress((void**)&xnr,  g_xn_r);
    cudaGetSymbolAddress((void**)&xni,  g_xn_i);
    cudaGetSymbolAddress((void**)&xnb,  g_xnb);
    cudaGetSymbolAddress((void**)&wb,   g_wb);
    cudaGetSymbolAddress((void**)&atb,  g_atb);
    cudaGetSymbolAddress((void**)&qkvb, g_qkvb);
    cudaGetSymbolAddress((void**)&outb, g_outb);
    cudaGetSymbolAddress((void**)&ffb,  g_ffb);

    cudaFuncSetAttribute(mma_gemm<0>, cudaFuncAttributeMaxDynamicSharedMemorySize, DSMEM_BYTES);
    cudaFuncSetAttribute(mma_gemm<3>, cudaFuncAttributeMaxDynamicSharedMemorySize, DSMEM_BYTES);
    cudaFuncSetAttribute(mma_gemm<4>, cudaFuncAttributeMaxDynamicSharedMemorySize, DSMEM_BYTES);
    cudaFuncSetAttribute(fused_attn_kernel, cudaFuncAttributeMaxDynamicSharedMemorySize, FUSED_SMEM + 128);

    copy_in_kernel<<<(PLN+255)/256, 256>>>(x_real, x_imag, xr, xi, PLN);
    conv_split_kernel<<<(WPL+255)/256, 256>>>(qkv_w_r, qkv_w_i, qkvb, WPL);
    conv_split_kernel<<<(WPL+255)/256, 256>>>(out_w_r, out_w_i, outb, WPL);
    conv_split_kernel<<<(WPL+255)/256, 256>>>(ff_w_r,  ff_w_i,  ffb,  WPL);

    for (int l = 0; l < DEPTH; l++){
        const size_t wo = (size_t)l*DIM*DIM;
        const size_t po = (size_t)l*DIM;

        // LN1 -> xn planes only
        cln_kernel<false><<<ROWS,128>>>(xr,xi, ln1_g_r+po, ln1_b_r+po, ln1_g_i+po, ln1_b_i+po, xnr,xni, xnb);
        // QKV: w = xn @ Wqkv^T -> w planes
        mma_gemm<0><<<dim3(8,16),256,DSMEM_BYTES>>>(
            xnb, PLN, DIM,  qkvb+wo, WPL, DIM,  DIM,
            nullptr,nullptr, DIM,  wb, PLN,
            nullptr,nullptr, nullptr,nullptr, nullptr,nullptr, 0);
        // fused attention -> at planes
        fused_attn_kernel<<<dim3(4,32),256,FUSED_SMEM + 128>>>(wb, atb);
        // x = at @ Wout^T + bias + x
        mma_gemm<3><<<dim3(8,16),256,DSMEM_BYTES>>>(
            atb, PLN, DIM,  outb+wo, WPL, DIM,  DIM,
            xr, xi, DIM,  nullptr,0,
            out_b_r+po, out_b_i+po, nullptr,nullptr, nullptr,nullptr, 0);
        // LN2 -> xn fp32 + planes
        cln_kernel<true><<<ROWS,128>>>(xr,xi, ln2_g_r+po, ln2_b_r+po, ln2_g_i+po, ln2_b_i+po, xnr,xni, xnb);
        // x = crelu(xn + ss*(xn @ Wff^T) - ss*lm)
        mma_gemm<4><<<dim3(8,16),256,DSMEM_BYTES>>>(
            xnb, PLN, DIM,  ffb+wo, WPL, DIM,  DIM,
            xr, xi, DIM,  nullptr,0,
            nullptr,nullptr, xnr, xni, step_sz, lambd, l);
    }

    copy_out_kernel<<<(PLN+255)/256, 256>>>(xr, xi, (float*)d_out, PLN);
}

// round 16
// speedup vs baseline: 1.0578x; 1.0578x over previous
#include <cuda_runtime.h>
#include <cuda_bf16.h>
#include <math.h>
#include <stdint.h>

#define BB 4
#define NN 512
#define DIM 512
#define HEADS 8
#define DH 64
#define DEPTH 4
#define ROWS (BB*NN)
#define ATT_SCALE 0.125f
#define LN_EPS 1e-5f
#define PLN (ROWS*DIM)          // 1048576
#define WPL (DEPTH*DIM*DIM)     // 1048576

// ---------------- scratch ----------------------------------------------------
__device__ float g_x_r [PLN];
__device__ float g_x_i [PLN];
__device__ float g_xn_r[PLN];
__device__ float g_xn_i[PLN];
// bf16 planes: 0=re_hi 1=re_lo 2=im_hi 3=im_lo
__device__ alignas(16) __nv_bfloat16 g_xnb [4*PLN];
__device__ alignas(16) __nv_bfloat16 g_wb  [4*PLN];
__device__ alignas(16) __nv_bfloat16 g_atb [4*PLN];
__device__ alignas(16) __nv_bfloat16 g_qkvb[4*WPL];
__device__ alignas(16) __nv_bfloat16 g_outb[4*WPL];
__device__ alignas(16) __nv_bfloat16 g_ffb [4*WPL];

// ---------------- helpers -----------------------------------------------------
__device__ __forceinline__ float warp_sum(float v){
    #pragma unroll
    for (int o=16;o;o>>=1) v += __shfl_xor_sync(0xffffffffu, v, o);
    return v;
}
__device__ __forceinline__ void cpa16(unsigned dst, const void* src){
    asm volatile("cp.async.cg.shared.global [%0], [%1], 16;" :: "r"(dst), "l"(src));
}
#define CP_COMMIT() asm volatile("cp.async.commit_group;")
#define CP_WAIT1()  asm volatile("cp.async.wait_group 1;")
#define CP_WAIT0()  asm volatile("cp.async.wait_group 0;")

__device__ __forceinline__ void ldsm4(unsigned &r0,unsigned &r1,unsigned &r2,unsigned &r3,unsigned a){
    asm volatile("ldmatrix.sync.aligned.m8n8.x4.shared.b16 {%0,%1,%2,%3}, [%4];"
        : "=r"(r0),"=r"(r1),"=r"(r2),"=r"(r3) : "r"(a));
}
__device__ __forceinline__ void ldsm4t(unsigned &r0,unsigned &r1,unsigned &r2,unsigned &r3,unsigned a){
    asm volatile("ldmatrix.sync.aligned.m8n8.x4.trans.shared.b16 {%0,%1,%2,%3}, [%4];"
        : "=r"(r0),"=r"(r1),"=r"(r2),"=r"(r3) : "r"(a));
}
__device__ __forceinline__ void mmabf(float* d, const unsigned* a, const unsigned* b){
    asm volatile("mma.sync.aligned.m16n8k16.row.col.f32.bf16.bf16.f32 "
        "{%0,%1,%2,%3}, {%4,%5,%6,%7}, {%8,%9}, {%0,%1,%2,%3};"
        : "+f"(d[0]),"+f"(d[1]),"+f"(d[2]),"+f"(d[3])
        : "r"(a[0]),"r"(a[1]),"r"(a[2]),"r"(a[3]), "r"(b[0]),"r"(b[1]));
}

__device__ __forceinline__ float frsqrt(float d){
    float x = __int_as_float(0x5f3759df - (__float_as_int(d) >> 1));
    x = x * fmaf(-0.5f*d, x*x, 1.5f);
    x = x * fmaf(-0.5f*d, x*x, 1.5f);
    return x;
}
__device__ __forceinline__ float fexp(float x){
    x = fmaxf(x, -87.0f);
    const float y = x * 1.4426950408889634f;
    const int   n = __float2int_rn(y);
    const float f = y - (float)n;
    float p = 1.3333558146e-3f;
    p = fmaf(p, f, 9.6181291076e-3f);
    p = fmaf(p, f, 5.5504108665e-2f);
    p = fmaf(p, f, 2.4022650696e-1f);
    p = fmaf(p, f, 6.9314718056e-1f);
    p = fmaf(p, f, 1.0f);
    return p * __int_as_float((n + 127) << 23);
}

__device__ __forceinline__ void split2(float x, float y, unsigned &hi, unsigned &lo){
    __nv_bfloat16 hx=__float2bfloat16_rn(x), hy=__float2bfloat16_rn(y);
    __nv_bfloat162 H = __halves2bfloat162(hx, hy);
    hi = *reinterpret_cast<unsigned*>(&H);
    __nv_bfloat16 lx=__float2bfloat16_rn(x-__bfloat162float(hx));
    __nv_bfloat16 ly=__float2bfloat16_rn(y-__bfloat162float(hy));
    __nv_bfloat162 L = __halves2bfloat162(lx, ly);
    lo = *reinterpret_cast<unsigned*>(&L);
}
__device__ __forceinline__ void store_split4(__nv_bfloat16* p, size_t pl, size_t o, float4 v){
    unsigned hi, lo;
    split2(v.x, v.y, hi, lo);
    *(unsigned*)(p+o) = hi; *(unsigned*)(p+pl+o) = lo;
    split2(v.z, v.w, hi, lo);
    *(unsigned*)(p+o+2) = hi; *(unsigned*)(p+pl+o+2) = lo;
}

// ---------------- small kernels -----------------------------------------------
__global__ void copy_in_kernel(const float* __restrict__ a, const float* __restrict__ b,
                               float* __restrict__ xr, float* __restrict__ xi, int n){
    int i = blockIdx.x*blockDim.x + threadIdx.x;
    if (i < n){ xr[i] = a[i]; xi[i] = b[i]; }
}
__global__ void copy_out_kernel(const float* __restrict__ xr, const float* __restrict__ xi,
                                float* __restrict__ out, int n){
    int i = blockIdx.x*blockDim.x + threadIdx.x;
    if (i < n){ out[i] = xr[i]; out[n+i] = xi[i]; }
}
__global__ void conv_split_kernel(const float* __restrict__ r, const float* __restrict__ im,
                                  __nv_bfloat16* __restrict__ dst, int n){
    int x = blockIdx.x*blockDim.x + threadIdx.x;
    if (x >= n) return;
    float v = r[x];
    __nv_bfloat16 h = __float2bfloat16_rn(v);
    dst[x] = h; dst[n + x] = __float2bfloat16_rn(v - __bfloat162float(h));
    v = im[x];
    h = __float2bfloat16_rn(v);
    dst[2*(size_t)n + x] = h; dst[3*(size_t)n + x] = __float2bfloat16_rn(v - __bfloat162float(h));
}

template<bool WF32>
__global__ __launch_bounds__(128)
void cln_kernel(const float* __restrict__ xr, const float* __restrict__ xi,
                const float* __restrict__ gr, const float* __restrict__ br,
                const float* __restrict__ gi, const float* __restrict__ bi,
                float* __restrict__ outr, float* __restrict__ outi,
                __nv_bfloat16* __restrict__ outb)
{
    const int row = blockIdx.x;
    const int t   = threadIdx.x;
    const float4 vr = reinterpret_cast<const float4*>(xr + (size_t)row*DIM)[t];
    const float4 vi = reinterpret_cast<const float4*>(xi + (size_t)row*DIM)[t];

    float sr  = vr.x+vr.y+vr.z+vr.w;
    float s2r = vr.x*vr.x+vr.y*vr.y+vr.z*vr.z+vr.w*vr.w;
    float si  = vi.x+vi.y+vi.z+vi.w;
    float s2i = vi.x*vi.x+vi.y*vi.y+vi.z*vi.z+vi.w*vi.w;

    sr = warp_sum(sr); s2r = warp_sum(s2r); si = warp_sum(si); s2i = warp_sum(s2i);

    __shared__ float red[4][4];
    const int wid = t >> 5, lane = t & 31;
    if (lane == 0){ red[wid][0]=sr; red[wid][1]=s2r; red[wid][2]=si; red[wid][3]=s2i; }
    __syncthreads();
    float tr=0,t2r=0,ti=0,t2i=0;
    #pragma unroll
    for (int w=0; w<4; w++){ tr+=red[w][0]; t2r+=red[w][1]; ti+=red[w][2]; t2i+=red[w][3]; }

    const float inv = 1.0f/DIM;
    const float mr = tr*inv,  vvr = t2r*inv - mr*mr;
    const float mi = ti*inv,  vvi = t2i*inv - mi*mi;
    const float rr = rsqrtf(vvr + LN_EPS);
    const float ri = rsqrtf(vvi + LN_EPS);

    const float4 g4r = reinterpret_cast<const float4*>(gr)[t];
    const float4 b4r = reinterpret_cast<const float4*>(br)[t];
    const float4 g4i = reinterpret_cast<const float4*>(gi)[t];
    const float4 b4i = reinterpret_cast<const float4*>(bi)[t];

    float4 orr, oii;
    orr.x = (vr.x-mr)*rr*g4r.x + b4r.x;  oii.x = (vi.x-mi)*ri*g4i.x + b4i.x;
    orr.y = (vr.y-mr)*rr*g4r.y + b4r.y;  oii.y = (vi.y-mi)*ri*g4i.y + b4i.y;
    orr.z = (vr.z-mr)*rr*g4r.z + b4r.z;  oii.z = (vi.z-mi)*ri*g4i.z + b4i.z;
    orr.w = (vr.w-mr)*rr*g4r.w + b4r.w;  oii.w = (vi.w-mi)*ri*g4i.w + b4i.w;
    if (WF32){
        reinterpret_cast<float4*>(outr + (size_t)row*DIM)[t] = orr;
        reinterpret_cast<float4*>(outi + (size_t)row*DIM)[t] = oii;
    }

    const size_t o = (size_t)row*DIM + 4*t;
    store_split4(outb,                 PLN, o, orr);
    store_split4(outb + (size_t)2*PLN, PLN, o, oii);
}

// ================= fused attention (dots + csoftmax + attn@V) ==================
// single-pass softmax: magnitudes are bounded (<<88), so no max subtraction needed
#define RSQ 144
#define QPLANE (128*RSQ)
#define KVPLANE (64*RSQ)
#define KVSTAGE (4*KVPLANE)
#define FUSED_SMEM (4*QPLANE + 2*KVSTAGE)   // 147456

__global__ __launch_bounds__(256, 1)
void fused_attn_kernel(const __nv_bfloat16* __restrict__ wb,
                       __nv_bfloat16* __restrict__ atb)
{
    extern __shared__ char dsmc[];
    const unsigned smQ  = ((unsigned)__cvta_generic_to_shared(dsmc) + 127u) & ~127u;
    const unsigned smKV = smQ + 4*QPLANE;

    const int tid = threadIdx.x;
    const int lane = tid & 31, wid = tid >> 5;
    const int wrow = wid * 16;
    const int m0 = blockIdx.x * 128;
    const int zb = blockIdx.y >> 3, zh = blockIdx.y & 7;
    const int qrow0 = zb*NN + m0;
    const int brow0 = zb*NN;
    const int colh  = zh*DH;

    #pragma unroll
    for (int t = 0; t < 16; t++){
        const int idx = tid + t*256;
        const int p = idx >> 10, rem = idx & 1023;
        const int r = rem >> 3, cc = rem & 7;
        cpa16(smQ + p*QPLANE + r*RSQ + cc*16,
              wb + (size_t)p*PLN + (size_t)(qrow0 + r)*DIM + colh + cc*8);
    }
    #pragma unroll
    for (int t = 0; t < 8; t++){
        const int idx = tid + t*256;
        const int p = idx >> 9, rem = idx & 511;
        const int r = rem >> 3, cc = rem & 7;
        cpa16(smKV + p*KVPLANE + r*RSQ + cc*16,
              wb + (size_t)p*PLN + (size_t)(brow0 + r)*DIM + colh + cc*8);
    }
    CP_COMMIT();

    float ore[8][4] = {}, oim[8][4] = {};
    float LA = 0.f, LB = 0.f;

    const int bg = lane >> 3;
    const int krow = (lane & 7) + ((lane >> 3) & 1)*8;
    const int nc8  = lane >> 4;

    for (int j = 0; j < 8; j++){
        CP_WAIT0();
        __syncthreads();
        const unsigned kvb = smKV + (unsigned)(j & 1)*KVSTAGE;
        if (j + 1 < 8){
            const unsigned kvn = smKV + (unsigned)((j+1) & 1)*KVSTAGE;
            #pragma unroll
            for (int t = 0; t < 8; t++){
                const int idx = tid + t*256;
                const int p = idx >> 9, rem = idx & 511;
                const int r = rem >> 3, cc = rem & 7;
                cpa16(kvn + p*KVPLANE + r*RSQ + cc*16,
                      wb + (size_t)p*PLN + (size_t)(brow0 + (j+1)*64 + r)*DIM + colh + cc*8);
            }
        }
        CP_COMMIT();

        float sre[8][4] = {}, sim[8][4] = {};
        #pragma unroll
        for (int kk = 0; kk < 4; kk++){
            unsigned qrh[4],qrl[4],qih[4],qil[4];
            const unsigned qa = smQ + (unsigned)(wrow + (lane & 15))*RSQ + kk*32 + (lane >> 4)*16;
            ldsm4(qrh[0],qrh[1],qrh[2],qrh[3], qa);
            ldsm4(qrl[0],qrl[1],qrl[2],qrl[3], qa + QPLANE);
            ldsm4(qih[0],qih[1],qih[2],qih[3], qa + 2*QPLANE);
            ldsm4(qil[0],qil[1],qil[2],qil[3], qa + 3*QPLANE);
            #pragma unroll
            for (int np = 0; np < 4; np++){
                const unsigned kb = kvb + (unsigned)(np*16 + ((bg & 2) << 2) + (lane & 7))*RSQ
                                        + kk*32 + (bg & 1)*16;
                unsigned krh[4],krl[4],kih[4],kil[4];
                ldsm4(krh[0],krh[1],krh[2],krh[3], kb);
                ldsm4(krl[0],krl[1],krl[2],krl[3], kb + KVPLANE);
                ldsm4(kih[0],kih[1],kih[2],kih[3], kb + 2*KVPLANE);
                ldsm4(kil[0],kil[1],kil[2],kil[3], kb + 3*KVPLANE);
                #pragma unroll
                for (int f = 0; f < 2; f++){
                    const int nf = 2*np + f;
                    unsigned bh[2] = {krh[2*f], krh[2*f+1]}, bl[2] = {krl[2*f], krl[2*f+1]};
                    unsigned ch[2] = {kih[2*f], kih[2*f+1]}, cl[2] = {kil[2*f], kil[2*f+1]};
                    mmabf(sre[nf], qrh, bh); mmabf(sre[nf], qrh, bl); mmabf(sre[nf], qrl, bh);
                    mmabf(sim[nf], qih, bh); mmabf(sim[nf], qih, bl); mmabf(sim[nf], qil, bh);
                    mmabf(sre[nf], qih, ch); mmabf(sre[nf], qih, cl); mmabf(sre[nf], qil, ch);
                    ch[0]^=0x80008000u; ch[1]^=0x80008000u; cl[0]^=0x80008000u; cl[1]^=0x80008000u;
                    mmabf(sim[nf], qrh, ch); mmabf(sim[nf], qrh, cl); mmabf(sim[nf], qrl, ch);
                }
            }
        }

        // single-pass softmax weights (no max subtraction; |m| bounded well below 88)
        #pragma unroll
        for (int nf = 0; nf < 8; nf++){
            #pragma unroll
            for (int q = 0; q < 4; q++){
                const float dd = sre[nf][q]*sre[nf][q] + sim[nf][q]*sim[nf][q];
                const float rs = frsqrt(dd);
                const float m  = (dd > 0.f) ? ATT_SCALE*dd*rs : 0.f;
                const float e  = fexp(m);
                const bool ok  = (dd > 0.f);
                const float pr = ok ? e*sre[nf][q]*rs : e;
                const float pi = ok ? e*sim[nf][q]*rs : 0.f;
                sre[nf][q] = pr; sim[nf][q] = pi;
                if (q < 2) LA += e; else LB += e;
            }
        }

        #pragma unroll
        for (int kt = 0; kt < 4; kt++){
            unsigned prh[4],prl[4],pih[4],pil[4];
            split2(sre[2*kt][0],   sre[2*kt][1],   prh[0], prl[0]);
            split2(sre[2*kt][2],   sre[2*kt][3],   prh[1], prl[1]);
            split2(sre[2*kt+1][0], sre[2*kt+1][1], prh[2], prl[2]);
            split2(sre[2*kt+1][2], sre[2*kt+1][3], prh[3], prl[3]);
            split2(sim[2*kt][0],   sim[2*kt][1],   pih[0], pil[0]);
            split2(sim[2*kt][2],   sim[2*kt][3],   pih[1], pil[1]);
            split2(sim[2*kt+1][0], sim[2*kt+1][1], pih[2], pil[2]);
            split2(sim[2*kt+1][2], sim[2*kt+1][3], pih[3], pil[3]);
            #pragma unroll
            for (int np2 = 0; np2 < 4; np2++){
                const unsigned vb = kvb + (unsigned)(kt*16 + krow)*RSQ
                                        + (unsigned)(np2*16 + nc8*8)*2;
                unsigned vrh[4],vrl[4],vih[4],vil[4];
                ldsm4t(vrh[0],vrh[1],vrh[2],vrh[3], vb);
                ldsm4t(vrl[0],vrl[1],vrl[2],vrl[3], vb + KVPLANE);
                ldsm4t(vih[0],vih[1],vih[2],vih[3], vb + 2*KVPLANE);
                ldsm4t(vil[0],vil[1],vil[2],vil[3], vb + 3*KVPLANE);
                #pragma unroll
                for (int f = 0; f < 2; f++){
                    const int nf = 2*np2 + f;
                    unsigned bh[2] = {vrh[2*f], vrh[2*f+1]}, bl[2] = {vrl[2*f], vrl[2*f+1]};
                    unsigned ch[2] = {vih[2*f], vih[2*f+1]}, cl[2] = {vil[2*f], vil[2*f+1]};
                    mmabf(ore[nf], prh, bh); mmabf(ore[nf], prh, bl); mmabf(ore[nf], prl, bh);
                    mmabf(oim[nf], pih, bh); mmabf(oim[nf], pih, bl); mmabf(oim[nf], pil, bh);
                    mmabf(oim[nf], prh, ch); mmabf(oim[nf], prh, cl); mmabf(oim[nf], prl, ch);
                    ch[0]^=0x80008000u; ch[1]^=0x80008000u; cl[0]^=0x80008000u; cl[1]^=0x80008000u;
                    mmabf(ore[nf], pih, ch); mmabf(ore[nf], pih, cl); mmabf(ore[nf], pil, ch);
                }
            }
        }
    }

    // reduce row sums across the quad once, then normalize and write
    LA += __shfl_xor_sync(0xffffffffu, LA, 1);
    LA += __shfl_xor_sync(0xffffffffu, LA, 2);
    LB += __shfl_xor_sync(0xffffffffu, LB, 1);
    LB += __shfl_xor_sync(0xffffffffu, LB, 2);
    const float invA = 1.0f / LA, invB = 1.0f / LB;
    const int gA = qrow0 + wrow + (lane >> 2);
    const int gB = gA + 8;
    #pragma unroll
    for (int nf = 0; nf < 8; nf++){
        const int c = colh + nf*8 + (lane & 3)*2;
        const size_t aA = (size_t)gA*DIM + c;
        const size_t aB = (size_t)gB*DIM + c;
        unsigned hi, lo;
        split2(ore[nf][0]*invA, ore[nf][1]*invA, hi, lo);
        *(unsigned*)(atb + aA) = hi; *(unsigned*)(atb + PLN + aA) = lo;
        split2(oim[nf][0]*invA, oim[nf][1]*invA, hi, lo);
        *(unsigned*)(atb + 2*(size_t)PLN + aA) = hi; *(unsigned*)(atb + 3*(size_t)PLN + aA) = lo;
        split2(ore[nf][2]*invB, ore[nf][3]*invB, hi, lo);
        *(unsigned*)(atb + aB) = hi; *(unsigned*)(atb + PLN + aB) = lo;
        split2(oim[nf][2]*invB, oim[nf][3]*invB, hi, lo);
        *(unsigned*)(atb + 2*(size_t)PLN + aB) = hi; *(unsigned*)(atb + 3*(size_t)PLN + aB) = lo;
    }
}

// ================= mma.sync bf16 complex GEMM (dense layers, BK=32) ============
#define RS 80                           // 64B data + 16B pad per row
#define APLANE (128*RS)                 // 10240
#define BPLANE (64*RS)                  // 5120
#define STAGE_B (4*APLANE + 4*BPLANE)   // 61440
#define NSTG 3
#define DSMEM_BYTES (NSTG*STAGE_B + 128)  // 184448

__device__ __forceinline__ void load_stage(unsigned sb,
    const __nv_bfloat16* A, size_t ap, int lda,
    const __nv_bfloat16* B, size_t bp, int ldb, int k0, int tid)
{
    #pragma unroll
    for (int i = 0; i < 8; i++){
        const int c = tid + i*256;          // 0..2047
        const int p = c >> 9, rem = c & 511;
        const int r = rem >> 2, cc = rem & 3;
        cpa16(sb + p*APLANE + r*RS + cc*16, A + (size_t)p*ap + (size_t)r*lda + k0 + cc*8);
    }
    #pragma unroll
    for (int i = 0; i < 4; i++){
        const int c = tid + i*256;          // 0..1023
        const int p = c >> 8, rem = c & 255;
        const int r = rem >> 2, cc = rem & 3;
        cpa16(sb + 4*APLANE + p*BPLANE + r*RS + cc*16, B + (size_t)p*bp + (size_t)r*ldb + k0 + cc*8);
    }
    CP_COMMIT();
}

__device__ __forceinline__ void compute_stage(unsigned sb, unsigned koff, int wm, int wn, int lane,
    float cre[2][4][4], float cim[2][4][4])
{
    const unsigned aoff = (unsigned)((lane & 15)*RS + (lane >> 4)*16) + koff;
    const int bg = lane >> 3;
    const unsigned boff  = (unsigned)((((bg & 2) << 2) + (lane & 7))*RS + (bg & 1)*16) + koff;

    unsigned Arh[2][4], Arl[2][4], Aih[2][4], Ail[2][4];
    #pragma unroll
    for (int mf=0; mf<2; mf++){
        const unsigned ab = sb + (unsigned)(wm + mf*16)*RS + aoff;
        ldsm4(Arh[mf][0],Arh[mf][1],Arh[mf][2],Arh[mf][3], ab);
        ldsm4(Arl[mf][0],Arl[mf][1],Arl[mf][2],Arl[mf][3], ab + APLANE);
        ldsm4(Aih[mf][0],Aih[mf][1],Aih[mf][2],Aih[mf][3], ab + 2*APLANE);
        ldsm4(Ail[mf][0],Ail[mf][1],Ail[mf][2],Ail[mf][3], ab + 3*APLANE);
    }
    unsigned Bh[4][2], Bl[4][2];
    #pragma unroll
    for (int np=0; np<2; np++){
        const unsigned bb = sb + 4*APLANE + (unsigned)(wn + np*16)*RS + boff;
        unsigned r0,r1,r2,r3;
        ldsm4(r0,r1,r2,r3, bb);
        Bh[2*np][0]=r0; Bh[2*np][1]=r1; Bh[2*np+1][0]=r2; Bh[2*np+1][1]=r3;
        ldsm4(r0,r1,r2,r3, bb + BPLANE);
        Bl[2*np][0]=r0; Bl[2*np][1]=r1; Bl[2*np+1][0]=r2; Bl[2*np+1][1]=r3;
    }
    #pragma unroll
    for (int mf=0; mf<2; mf++)
    #pragma unroll
    for (int nf=0; nf<4; nf++){
        mmabf(cre[mf][nf], Arh[mf], Bh[nf]);
        mmabf(cre[mf][nf], Arh[mf], Bl[nf]);
        mmabf(cre[mf][nf], Arl[mf], Bh[nf]);
        mmabf(cim[mf][nf], Aih[mf], Bh[nf]);
        mmabf(cim[mf][nf], Aih[mf], Bl[nf]);
        mmabf(cim[mf][nf], Ail[mf], Bh[nf]);
    }
    #pragma unroll
    for (int np=0; np<2; np++){
        const unsigned bb = sb + 4*APLANE + 2*BPLANE + (unsigned)(wn + np*16)*RS + boff;
        unsigned r0,r1,r2,r3;
        ldsm4(r0,r1,r2,r3, bb);
        Bh[2*np][0]=r0; Bh[2*np][1]=r1; Bh[2*np+1][0]=r2; Bh[2*np+1][1]=r3;
        ldsm4(r0,r1,r2,r3, bb + BPLANE);
        Bl[2*np][0]=r0; Bl[2*np][1]=r1; Bl[2*np+1][0]=r2; Bl[2*np+1][1]=r3;
    }
    #pragma unroll
    for (int mf=0; mf<2; mf++)
    #pragma unroll
    for (int nf=0; nf<4; nf++){
        mmabf(cim[mf][nf], Arh[mf], Bh[nf]);
        mmabf(cim[mf][nf], Arh[mf], Bl[nf]);
        mmabf(cim[mf][nf], Arl[mf], Bh[nf]);
    }
    #pragma unroll
    for (int nf=0; nf<4; nf++){
        Bh[nf][0]^=0x80008000u; Bh[nf][1]^=0x80008000u;
        Bl[nf][0]^=0x80008000u; Bl[nf][1]^=0x80008000u;
    }
    #pragma unroll
    for (int mf=0; mf<2; mf++)
    #pragma unroll
    for (int nf=0; nf<4; nf++){
        mmabf(cre[mf][nf], Aih[mf], Bh[nf]);
        mmabf(cre[mf][nf], Aih[mf], Bl[nf]);
        mmabf(cre[mf][nf], Ail[mf], Bh[nf]);
    }
}

// EPI: 0=planes out, 3=OUT (x+=acc+bias), 4=FF (crelu)
template<int EPI>
__global__ __launch_bounds__(256, 1)
void mma_gemm(const __nv_bfloat16* __restrict__ Ab, size_t ap, int lda,
              const __nv_bfloat16* __restrict__ Bb, size_t bp, int ldb,
              int K,
              float* Cr, float* Ci, int ldc,
              __nv_bfloat16* Ob, size_t op,
              const float* __restrict__ biasR, const float* __restrict__ biasI,
              const float* __restrict__ Xr, const float* __restrict__ Xi,
              const float* __restrict__ ssp, const float* __restrict__ lmp, int layer)
{
    extern __shared__ char dsmc[];
    const unsigned base = ((unsigned)__cvta_generic_to_shared(dsmc) + 127u) & ~127u;

    const int tid = threadIdx.x;
    const int lane = tid & 31, wid = tid >> 5;
    const int wm = (wid & 3)*32, wn = (wid >> 2)*32;
    const int m0 = blockIdx.y * 128, n0 = blockIdx.x * 64;

    const __nv_bfloat16* At = Ab + (size_t)m0*lda;
    const __nv_bfloat16* Bt = Bb + (size_t)n0*ldb;

    float cre[2][4][4] = {}, cim[2][4][4] = {};

    const int NIT = K >> 5;     // 32-k slabs
    load_stage(base, At, ap, lda, Bt, bp, ldb, 0, tid);
    if (NIT > 1) load_stage(base + STAGE_B, At, ap, lda, Bt, bp, ldb, 32, tid);
    else CP_COMMIT();

    int sidx = 0;
    for (int it = 0; it < NIT; it++){
        if (it + 1 < NIT) CP_WAIT1(); else CP_WAIT0();
        __syncthreads();
        if (it + 2 < NIT){
            int sn = sidx + 2; if (sn >= NSTG) sn -= NSTG;
            load_stage(base + (unsigned)sn*STAGE_B, At, ap, lda, Bt, bp, ldb, (it+2) << 5, tid);
        } else {
            CP_COMMIT();
        }
        const unsigned sb = base + (unsigned)sidx*STAGE_B;
        compute_stage(sb, 0u,  wm, wn, lane, cre, cim);
        compute_stage(sb, 32u, wm, wn, lane, cre, cim);
        sidx++; if (sidx == NSTG) sidx = 0;
    }

    float ss = 0.f, lm = 0.f;
    if (EPI == 4){ ss = log1pf(expf(ssp[layer])); lm = log1pf(expf(lmp[layer])); }

    #pragma unroll
    for (int mf=0; mf<2; mf++)
    #pragma unroll
    for (int nf=0; nf<4; nf++){
        const int row0 = m0 + wm + mf*16 + (lane >> 2);
        const int col  = n0 + wn + nf*8 + (lane & 3)*2;
        #pragma unroll
        for (int h=0; h<2; h++){
            const int r = row0 + h*8;
            float vr0 = cre[mf][nf][2*h];
            float vr1 = cre[mf][nf][2*h+1];
            float vi0 = cim[mf][nf][2*h];
            float vi1 = cim[mf][nf][2*h+1];
            const size_t a = (size_t)r*ldc + col;
            if (EPI == 3){
                Cr[a]   = vr0 + biasR[col]   + Cr[a];
                Cr[a+1] = vr1 + biasR[col+1] + Cr[a+1];
                Ci[a]   = vi0 + biasI[col]   + Ci[a];
                Ci[a+1] = vi1 + biasI[col+1] + Ci[a+1];
            } else if (EPI == 4){
                Cr[a]   = fmaxf(fmaf(ss, vr0, Xr[a])   - ss*lm, 0.f);
                Cr[a+1] = fmaxf(fmaf(ss, vr1, Xr[a+1]) - ss*lm, 0.f);
                Ci[a]   = fmaxf(fmaf(ss, vi0, Xi[a]),   0.f);
                Ci[a+1] = fmaxf(fmaf(ss, vi1, Xi[a+1]), 0.f);
            } else {
                unsigned hi, lo;
                split2(vr0, vr1, hi, lo);
                *(unsigned*)(Ob + a) = hi; *(unsigned*)(Ob + op + a) = lo;
                split2(vi0, vi1, hi, lo);
                *(unsigned*)(Ob + 2*op + a) = hi; *(unsigned*)(Ob + 3*op + a) = lo;
            }
        }
    }
}

// ---------------- launch --------------------------------------------------------
extern "C" void kernel_launch(void* const* d_in, const int* in_sizes, int n_in,
                              void* d_out, int out_size)
{
    const float* x_real   = (const float*)d_in[0];
    const float* x_imag   = (const float*)d_in[1];
    const float* ln1_g_r  = (const float*)d_in[2];
    const float* ln1_b_r  = (const float*)d_in[3];
    const float* ln1_g_i  = (const float*)d_in[4];
    const float* ln1_b_i  = (const float*)d_in[5];
    const float* ln2_g_r  = (const float*)d_in[6];
    const float* ln2_b_r  = (const float*)d_in[7];
    const float* ln2_g_i  = (const float*)d_in[8];
    const float* ln2_b_i  = (const float*)d_in[9];
    const float* qkv_w_r  = (const float*)d_in[10];
    const float* qkv_w_i  = (const float*)d_in[11];
    const float* out_w_r  = (const float*)d_in[12];
    const float* out_w_i  = (const float*)d_in[13];
    const float* out_b_r  = (const float*)d_in[14];
    const float* out_b_i  = (const float*)d_in[15];
    const float* ff_w_r   = (const float*)d_in[16];
    const float* ff_w_i   = (const float*)d_in[17];
    const float* step_sz  = (const float*)d_in[18];
    const float* lambd    = (const float*)d_in[19];

    float *xr,*xi,*xnr,*xni;
    __nv_bfloat16 *xnb,*wb,*atb,*qkvb,*outb,*ffb;
    cudaGetSymbolAddress((void**)&xr,   g_x_r);
    cudaGetSymbolAddress((void**)&xi,   g_x_i);
    cudaGetSymbolAddress((void**)&xnr,  g_xn_r);
    cudaGetSymbolAddress((void**)&xni,  g_xn_i);
    cudaGetSymbolAddress((void**)&xnb,  g_xnb);
    cudaGetSymbolAddress((void**)&wb,   g_wb);
    cudaGetSymbolAddress((void**)&atb,  g_atb);
    cudaGetSymbolAddress((void**)&qkvb, g_qkvb);
    cudaGetSymbolAddress((void**)&outb, g_outb);
    cudaGetSymbolAddress((void**)&ffb,  g_ffb);

    cudaFuncSetAttribute(mma_gemm<0>, cudaFuncAttributeMaxDynamicSharedMemorySize, DSMEM_BYTES);
    cudaFuncSetAttribute(mma_gemm<3>, cudaFuncAttributeMaxDynamicSharedMemorySize, DSMEM_BYTES);
    cudaFuncSetAttribute(mma_gemm<4>, cudaFuncAttributeMaxDynamicSharedMemorySize, DSMEM_BYTES);
    cudaFuncSetAttribute(fused_attn_kernel, cudaFuncAttributeMaxDynamicSharedMemorySize, FUSED_SMEM + 128);

    copy_in_kernel<<<(PLN+255)/256, 256>>>(x_real, x_imag, xr, xi, PLN);
    conv_split_kernel<<<(WPL+255)/256, 256>>>(qkv_w_r, qkv_w_i, qkvb, WPL);
    conv_split_kernel<<<(WPL+255)/256, 256>>>(out_w_r, out_w_i, outb, WPL);
    conv_split_kernel<<<(WPL+255)/256, 256>>>(ff_w_r,  ff_w_i,  ffb,  WPL);

    for (int l = 0; l < DEPTH; l++){
        const size_t wo = (size_t)l*DIM*DIM;
        const size_t po = (size_t)l*DIM;

        // LN1 -> xn planes only
        cln_kernel<false><<<ROWS,128>>>(xr,xi, ln1_g_r+po, ln1_b_r+po, ln1_g_i+po, ln1_b_i+po, xnr,xni, xnb);
        // QKV: w = xn @ Wqkv^T -> w planes
        mma_gemm<0><<<dim3(8,16),256,DSMEM_BYTES>>>(
            xnb, PLN, DIM,  qkvb+wo, WPL, DIM,  DIM,
            nullptr,nullptr, DIM,  wb, PLN,
            nullptr,nullptr, nullptr,nullptr, nullptr,nullptr, 0);
        // fused attention -> at planes
        fused_attn_kernel<<<dim3(4,32),256,FUSED_SMEM + 128>>>(wb, atb);
        // x = at @ Wout^T + bias + x
        mma_gemm<3><<<dim3(8,16),256,DSMEM_BYTES>>>(
            atb, PLN, DIM,  outb+wo, WPL, DIM,  DIM,
            xr, xi, DIM,  nullptr,0,
            out_b_r+po, out_b_i+po, nullptr,nullptr, nullptr,nullptr, 0);
        // LN2 -> xn fp32 + planes
        cln_kernel<true><<<ROWS,128>>>(xr,xi, ln2_g_r+po, ln2_b_r+po, ln2_g_i+po, ln2_b_i+po, xnr,xni, xnb);
        // x = crelu(xn + ss*(xn @ Wff^T) - ss*lm)
        mma_gemm<4><<<dim3(8,16),256,DSMEM_BYTES>>>(
            xnb, PLN, DIM,  ffb+wo, WPL, DIM,  DIM,
            xr, xi, DIM,  nullptr,0,
            nullptr,nullptr, xnr, xni, step_sz, lambd, l);
    }

    copy_out_kernel<<<(PLN+255)/256, 256>>>(xr, xi, (float*)d_out, PLN);
}